// round 13
// baseline (speedup 1.0000x reference)
#include <cuda_runtime.h>
#include <math.h>
#include <stdint.h>

#define N_NODES 50000
#define HC 128
#define NHEAD 2
#define CDIM 64
#define E_EDGES 800000
#define ETOT (E_EDGES + N_NODES)
#define NEG_SLOPE 0.2f
#define EPS_GN 1e-5f

// ---------------- scratch (static device globals; no allocations) ------------
__device__ float d_xl[N_NODES * HC];
__device__ float d_xr[N_NODES * HC];
__device__ float d_feat[N_NODES * HC];
__device__ float d_acc[N_NODES * HC];
__device__ float d_sum[HC];
__device__ float d_sumsq[HC];
// CSR (built once per launch, reused by both layers)
__device__ int d_deg[N_NODES];
__device__ int d_ptr[N_NODES + 1];
__device__ int d_cursor[N_NODES];
__device__ int d_adj[ETOT];

// ---------------- tf32 helpers ----------------------------------------------
__device__ __forceinline__ uint32_t f2tf32(float x) {
    uint32_t r;
    asm("cvt.rna.tf32.f32 %0, %1;" : "=r"(r) : "f"(x));
    return r;
}

__device__ __forceinline__ void mma_tf32(float* c, const uint32_t* a,
                                         uint32_t b0, uint32_t b1) {
    asm volatile(
        "mma.sync.aligned.m16n8k8.row.col.f32.tf32.tf32.f32 "
        "{%0,%1,%2,%3}, {%4,%5,%6,%7}, {%8,%9}, {%0,%1,%2,%3};\n"
        : "+f"(c[0]), "+f"(c[1]), "+f"(c[2]), "+f"(c[3])
        : "r"(a[0]), "r"(a[1]), "r"(a[2]), "r"(a[3]), "r"(b0), "r"(b1));
}

// ------- dual GEMM on tensor cores (3xTF32 split): Yl=X@Wl+bl, Yr=X@Wr+br ----
// block: 256 threads (8 warps), tile M=64 x N=256 (Wl|Wr concat), K-chunk 16.
// smem holds fragment-ordered tf32 hi/lo copies -> conflict-free LDS.
__global__ __launch_bounds__(256) void gemm_dual_tc(
    const float* __restrict__ X,
    const float* __restrict__ Wl, const float* __restrict__ bl,
    const float* __restrict__ Wr, const float* __restrict__ br,
    float* __restrict__ Yl, float* __restrict__ Yr)
{
    // A: mtile(4) x k8(2) x reg(4) x lane(32) = 1024 words per split
    // B: k8(2) x ngrp(32) x [lane*2 + reg](64) = 4096 words per split
    __shared__ uint32_t Ah[1024], Al[1024];
    __shared__ uint32_t Bh[4096], Bl[4096];

    const int tid = threadIdx.x;
    const int wid = tid >> 5, lane = tid & 31;
    const int wr = wid >> 2;          // warp row (0..1): 32 M-rows each
    const int wc = wid & 3;           // warp col (0..3): 64 N-cols each
    const int r0 = blockIdx.x * 64;

    float acc[2][8][4];
#pragma unroll
    for (int i = 0; i < 2; i++)
#pragma unroll
        for (int j = 0; j < 8; j++)
#pragma unroll
            for (int r = 0; r < 4; r++) acc[i][j][r] = 0.f;

    // --- precomputed per-thread load geometry (constant across chunks) ---
    // X: thread -> one float4: row = tid>>2 (0..63), k-quad c4x = tid&3
    const int xrow = tid >> 2;
    const int c4x = tid & 3;
    const int xgr = r0 + xrow;
    const bool xok = (xgr < N_NODES);
    {
        // nothing else precomputed; index math is cheap and latency-hidden
    }

    for (int kc = 0; kc < 128; kc += 16) {
        // ---- stage X chunk (64 x 16) as A fragments ----
        {
            float4 xv = make_float4(0.f, 0.f, 0.f, 0.f);
            if (xok) xv = *(const float4*)&X[xgr * 128 + kc + c4x * 4];
            int mt = xrow >> 4, rin = xrow & 15;
            int g = rin & 7, hi8 = rin >> 3;
            int k0 = c4x * 4;
            int k8 = k0 >> 3;
            int k4c = (k0 & 7) >> 2;
            int reg = hi8 + 2 * k4c;
            int base = ((mt * 2 + k8) * 4 + reg) * 32 + g * 4;  // + e
            float xs[4] = {xv.x, xv.y, xv.z, xv.w};
#pragma unroll
            for (int e = 0; e < 4; e++) {
                uint32_t hb = f2tf32(xs[e]);
                float lo = xs[e] - __uint_as_float(hb);
                Ah[base + e] = hb;
                Al[base + e] = f2tf32(lo);
            }
        }
        // ---- stage W chunks (16 x 128 each of Wl, Wr) as B fragments ----
#pragma unroll
        for (int i = 0; i < 2; i++) {
            int f = i * 256 + tid;
            int k = f >> 5;              // 0..15
            int c4 = f & 31;             // col quad; n = c4*4 + e
            int tk = k & 3;
            int reg = (k & 7) >> 2;
            int k8 = k >> 3;
            int gbase = (c4 & 1) * 4;    // g for e = 0
            int ngrp = c4 >> 1;          // 0..15 within one 128-col matrix
            int b0 = (k8 * 32 + ngrp) * 64 + (gbase * 4 + tk) * 2 + reg; // + e*8
            float4 wv = *(const float4*)&Wl[(kc + k) * 128 + c4 * 4];
            float ws[4] = {wv.x, wv.y, wv.z, wv.w};
#pragma unroll
            for (int e = 0; e < 4; e++) {
                uint32_t hb = f2tf32(ws[e]);
                float lo = ws[e] - __uint_as_float(hb);
                Bh[b0 + e * 8] = hb;
                Bl[b0 + e * 8] = f2tf32(lo);
            }
            int b1 = (k8 * 32 + (ngrp + 16)) * 64 + (gbase * 4 + tk) * 2 + reg;
            wv = *(const float4*)&Wr[(kc + k) * 128 + c4 * 4];
            ws[0] = wv.x; ws[1] = wv.y; ws[2] = wv.z; ws[3] = wv.w;
#pragma unroll
            for (int e = 0; e < 4; e++) {
                uint32_t hb = f2tf32(ws[e]);
                float lo = ws[e] - __uint_as_float(hb);
                Bh[b1 + e * 8] = hb;
                Bl[b1 + e * 8] = f2tf32(lo);
            }
        }
        __syncthreads();

        // ---- compute: 2 k8-steps of m16n8k8 ----
#pragma unroll
        for (int k8 = 0; k8 < 2; k8++) {
            uint32_t ah[2][4], al[2][4];
#pragma unroll
            for (int i = 0; i < 2; i++) {
                int mt = wr * 2 + i;
                int base = (mt * 2 + k8) * 128 + lane;
#pragma unroll
                for (int r = 0; r < 4; r++) {
                    ah[i][r] = Ah[base + r * 32];
                    al[i][r] = Al[base + r * 32];
                }
            }
#pragma unroll
            for (int j = 0; j < 8; j++) {
                int ngrp = wc * 8 + j;
                int bb = (k8 * 32 + ngrp) * 64 + lane * 2;
                uint2 bhv = *(const uint2*)&Bh[bb];
                uint2 blv = *(const uint2*)&Bl[bb];
#pragma unroll
                for (int i = 0; i < 2; i++) {
                    mma_tf32(acc[i][j], ah[i], bhv.x, bhv.y);  // hi*hi
                    mma_tf32(acc[i][j], ah[i], blv.x, blv.y);  // hi*lo
                    mma_tf32(acc[i][j], al[i], bhv.x, bhv.y);  // lo*hi
                }
            }
        }
        __syncthreads();
    }

    // ---- epilogue: bias + store (c0,c1)/(c2,c3) as float2 ----
    const float* bo = (wc < 2) ? bl : br;
    float* Yo = (wc < 2) ? Yl : Yr;
    const int ncol0 = (wc & 1) * 64;
    const int g = lane >> 2, t = lane & 3;
#pragma unroll
    for (int i = 0; i < 2; i++) {
        int rowa = r0 + wr * 32 + i * 16 + g;
        int rowb = rowa + 8;
#pragma unroll
        for (int j = 0; j < 8; j++) {
            int col = ncol0 + j * 8 + t * 2;
            float2 bb = *(const float2*)&bo[col];
            if (rowa < N_NODES) {
                float2 o = make_float2(acc[i][j][0] + bb.x, acc[i][j][1] + bb.y);
                *(float2*)&Yo[rowa * 128 + col] = o;
            }
            if (rowb < N_NODES) {
                float2 o = make_float2(acc[i][j][2] + bb.x, acc[i][j][3] + bb.y);
                *(float2*)&Yo[rowb * 128 + col] = o;
            }
        }
    }
}

// ---------------- CSR build --------------------------------------------------
__global__ void csr_deg_init()
{
    int i = blockIdx.x * blockDim.x + threadIdx.x;
    if (i < N_NODES) d_deg[i] = 1;   // self loop counted up front
}

__global__ void csr_count(const int* __restrict__ ei)
{
    int i = blockIdx.x * blockDim.x + threadIdx.x;
    if (i < E_EDGES) atomicAdd(&d_deg[ei[E_EDGES + i]], 1);
}

__global__ __launch_bounds__(1024) void csr_scan()
{
    __shared__ int part[1024];
    const int t = threadIdx.x;
    const int CH = (N_NODES + 1023) / 1024;         // 49
    int beg = t * CH;
    int end = beg + CH; if (end > N_NODES) end = N_NODES;
    if (beg > N_NODES) beg = N_NODES;

    int s = 0;
    for (int i = beg; i < end; i++) s += d_deg[i];
    part[t] = s;
    __syncthreads();
    for (int off = 1; off < 1024; off <<= 1) {
        int v = (t >= off) ? part[t - off] : 0;
        __syncthreads();
        part[t] += v;
        __syncthreads();
    }
    int run = (t == 0) ? 0 : part[t - 1];
    for (int i = beg; i < end; i++) {
        d_ptr[i] = run;
        d_cursor[i] = run;
        run += d_deg[i];
    }
    if (t == 1023) d_ptr[N_NODES] = part[1023];
}

__global__ void csr_scatter(const int* __restrict__ ei)
{
    int i = blockIdx.x * blockDim.x + threadIdx.x;
    if (i >= ETOT) return;
    int s, d;
    if (i < E_EDGES) { s = ei[i]; d = ei[E_EDGES + i]; }
    else             { s = d = i - E_EDGES; }
    int pos = atomicAdd(&d_cursor[d], 1);
    d_adj[pos] = s;
}

// ---------------- fused per-dst GATv2 (no-shift softmax, 2-way unroll) ------
// one warp per dst node; xl gathered once; iterations fully independent.
__global__ __launch_bounds__(256) void gat_dst(
    const float* __restrict__ att, const float* __restrict__ bias)
{
    const int w = (blockIdx.x * blockDim.x + threadIdx.x) >> 5;
    const int lane = threadIdx.x & 31;
    if (w >= N_NODES) return;

    const int beg = d_ptr[w];
    const int end = d_ptr[w + 1];
    const int ch = lane * 4;

    const float4 xr4 = *(const float4*)&d_xr[(size_t)w * HC + ch];
    const float4 av  = *(const float4*)&att[ch];

    float rsum = 0.f;
    float4 acc = make_float4(0.f, 0.f, 0.f, 0.f);

    int k = beg;
    for (; k + 1 < end; k += 2) {
        int s0 = d_adj[k];
        int s1 = d_adj[k + 1];
        float4 a0 = *(const float4*)&d_xl[(size_t)s0 * HC + ch];
        float4 a1 = *(const float4*)&d_xl[(size_t)s1 * HC + ch];

        float m, p0 = 0.f, p1 = 0.f;
        m = a0.x + xr4.x; m = (m > 0.f) ? m : NEG_SLOPE * m; p0 += m * av.x;
        m = a0.y + xr4.y; m = (m > 0.f) ? m : NEG_SLOPE * m; p0 += m * av.y;
        m = a0.z + xr4.z; m = (m > 0.f) ? m : NEG_SLOPE * m; p0 += m * av.z;
        m = a0.w + xr4.w; m = (m > 0.f) ? m : NEG_SLOPE * m; p0 += m * av.w;
        m = a1.x + xr4.x; m = (m > 0.f) ? m : NEG_SLOPE * m; p1 += m * av.x;
        m = a1.y + xr4.y; m = (m > 0.f) ? m : NEG_SLOPE * m; p1 += m * av.y;
        m = a1.z + xr4.z; m = (m > 0.f) ? m : NEG_SLOPE * m; p1 += m * av.z;
        m = a1.w + xr4.w; m = (m > 0.f) ? m : NEG_SLOPE * m; p1 += m * av.w;

        p0 += __shfl_xor_sync(0xffffffffu, p0, 8, 16);
        p1 += __shfl_xor_sync(0xffffffffu, p1, 8, 16);
        p0 += __shfl_xor_sync(0xffffffffu, p0, 4, 16);
        p1 += __shfl_xor_sync(0xffffffffu, p1, 4, 16);
        p0 += __shfl_xor_sync(0xffffffffu, p0, 2, 16);
        p1 += __shfl_xor_sync(0xffffffffu, p1, 2, 16);
        p0 += __shfl_xor_sync(0xffffffffu, p0, 1, 16);
        p1 += __shfl_xor_sync(0xffffffffu, p1, 1, 16);

        float w0 = __expf(p0);
        float w1 = __expf(p1);
        rsum += w0 + w1;
        acc.x += w0 * a0.x + w1 * a1.x;
        acc.y += w0 * a0.y + w1 * a1.y;
        acc.z += w0 * a0.z + w1 * a1.z;
        acc.w += w0 * a0.w + w1 * a1.w;
    }
    if (k < end) {
        int s0 = d_adj[k];
        float4 a0 = *(const float4*)&d_xl[(size_t)s0 * HC + ch];
        float m, p0 = 0.f;
        m = a0.x + xr4.x; m = (m > 0.f) ? m : NEG_SLOPE * m; p0 += m * av.x;
        m = a0.y + xr4.y; m = (m > 0.f) ? m : NEG_SLOPE * m; p0 += m * av.y;
        m = a0.z + xr4.z; m = (m > 0.f) ? m : NEG_SLOPE * m; p0 += m * av.z;
        m = a0.w + xr4.w; m = (m > 0.f) ? m : NEG_SLOPE * m; p0 += m * av.w;
        p0 += __shfl_xor_sync(0xffffffffu, p0, 8, 16);
        p0 += __shfl_xor_sync(0xffffffffu, p0, 4, 16);
        p0 += __shfl_xor_sync(0xffffffffu, p0, 2, 16);
        p0 += __shfl_xor_sync(0xffffffffu, p0, 1, 16);
        float w0 = __expf(p0);
        rsum += w0;
        acc.x += w0 * a0.x;
        acc.y += w0 * a0.y;
        acc.z += w0 * a0.z;
        acc.w += w0 * a0.w;
    }

    const float invd = 1.f / (rsum + 1e-16f);
    const float4 bv = *(const float4*)&bias[ch];
    float4 o;
    o.x = acc.x * invd + bv.x;
    o.y = acc.y * invd + bv.y;
    o.z = acc.z * invd + bv.z;
    o.w = acc.w * invd + bv.w;
    *(float4*)&d_acc[(size_t)w * HC + ch] = o;
}

// ---------------- GraphNorm stats: sum + sumsq in one pass ------------------
__global__ void zero_stats()
{
    int c = threadIdx.x;
    if (c < HC) { d_sum[c] = 0.f; d_sumsq[c] = 0.f; }
}

__global__ void colstats()
{
    int c = threadIdx.x;  // 128 threads
    float s = 0.f, q = 0.f;
    for (int r = blockIdx.x; r < N_NODES; r += gridDim.x) {
        float v = d_acc[r * HC + c];
        s += v;
        q += v * v;
    }
    atomicAdd(&d_sum[c], s);
    atomicAdd(&d_sumsq[c], q);
}

__global__ void norm_relu(const float* __restrict__ g,
                          const float* __restrict__ be,
                          const float* __restrict__ ms)
{
    int idx = blockIdx.x * blockDim.x + threadIdx.x;
    if (idx >= N_NODES * HC) return;
    int c = idx & 127;
    float mean = d_sum[c] * (1.f / N_NODES);
    float msq  = d_sumsq[c] * (1.f / N_NODES);
    float mm = ms[c] * mean;
    float var = msq - 2.f * mm * mean + mm * mm;   // E[(x - ms*mean)^2]
    float inv = rsqrtf(var + EPS_GN);
    float y = g[c] * (d_acc[idx] - mm) * inv + be[c];
    d_feat[idx] = (y > 0.f) ? y : 0.f;
}

// ---------------- fused MLP head: relu(feat@W1+b1)@W2+b2 --------------------
__global__ __launch_bounds__(256) void mlp_head(
    const float* __restrict__ W1, const float* __restrict__ b1,
    const float* __restrict__ W2, const float* __restrict__ b2,
    float* __restrict__ out)
{
    __shared__ float W1s[128 * 64];
    __shared__ float W2s[128];
    __shared__ float b1s[64];
    __shared__ float xs[8][128];

    int tid = threadIdx.x;
    for (int i = tid; i < 128 * 64; i += 256) W1s[i] = W1[i];
    if (tid < 128) W2s[tid] = W2[tid];
    if (tid < 64) b1s[tid] = b1[tid];
    __syncthreads();

    int w = tid >> 5, lane = tid & 31;
    float bb0 = b2[0], bb1 = b2[1];

    for (int n = blockIdx.x * 8 + w; n < N_NODES; n += gridDim.x * 8) {
        *(float4*)&xs[w][lane * 4] =
            *(const float4*)&d_feat[(size_t)n * HC + lane * 4];
        __syncwarp();

        float h0 = b1s[lane], h1 = b1s[lane + 32];
#pragma unroll
        for (int k = 0; k < 128; k++) {
            float x = xs[w][k];
            h0 += x * W1s[k * 64 + lane];
            h1 += x * W1s[k * 64 + lane + 32];
        }
        h0 = (h0 > 0.f) ? h0 : 0.f;
        h1 = (h1 > 0.f) ? h1 : 0.f;

        float p0 = h0 * W2s[lane * 2]     + h1 * W2s[(lane + 32) * 2];
        float p1 = h0 * W2s[lane * 2 + 1] + h1 * W2s[(lane + 32) * 2 + 1];
#pragma unroll
        for (int off = 16; off > 0; off >>= 1) {
            p0 += __shfl_down_sync(0xffffffffu, p0, off);
            p1 += __shfl_down_sync(0xffffffffu, p1, off);
        }
        if (lane == 0) {
            out[n * 2]     = p0 + bb0;
            out[n * 2 + 1] = p1 + bb1;
        }
        __syncwarp();
    }
}

// ---------------- driver -----------------------------------------------------
extern "C" void kernel_launch(void* const* d_in, const int* in_sizes, int n_in,
                              void* d_out, int out_size)
{
    const float* x      = (const float*)d_in[0];
    const int*   ei     = (const int*)d_in[1];
    const float* Wl0 = (const float*)d_in[2];
    const float* bl0 = (const float*)d_in[3];
    const float* Wr0 = (const float*)d_in[4];
    const float* br0 = (const float*)d_in[5];
    const float* att0  = (const float*)d_in[6];
    const float* bias0 = (const float*)d_in[7];
    const float* Wl1 = (const float*)d_in[8];
    const float* bl1 = (const float*)d_in[9];
    const float* Wr1 = (const float*)d_in[10];
    const float* br1 = (const float*)d_in[11];
    const float* att1  = (const float*)d_in[12];
    const float* bias1 = (const float*)d_in[13];
    const float* g0  = (const float*)d_in[14];
    const float* be0 = (const float*)d_in[15];
    const float* ms0 = (const float*)d_in[16];
    const float* g1  = (const float*)d_in[17];
    const float* be1 = (const float*)d_in[18];
    const float* ms1 = (const float*)d_in[19];
    const float* W1 = (const float*)d_in[20];
    const float* b1 = (const float*)d_in[21];
    const float* W2 = (const float*)d_in[22];
    const float* b2 = (const float*)d_in[23];
    float* out = (float*)d_out;

    float *p_xl, *p_xr, *p_feat;
    cudaGetSymbolAddress((void**)&p_xl,   d_xl);
    cudaGetSymbolAddress((void**)&p_xr,   d_xr);
    cudaGetSymbolAddress((void**)&p_feat, d_feat);

    const int gemm_grid = (N_NODES + 63) / 64;
    const int nrm_grid  = (N_NODES * HC + 255) / 256;
    const int gat_grid  = (N_NODES * 32 + 255) / 256;   // warp per dst

    // ---------- CSR build (once; reused by both layers) ----------
    csr_deg_init<<<(N_NODES + 255) / 256, 256>>>();
    csr_count<<<(E_EDGES + 255) / 256, 256>>>(ei);
    csr_scan<<<1, 1024>>>();
    csr_scatter<<<(ETOT + 255) / 256, 256>>>(ei);

    // ---------- layer 0 ----------
    gemm_dual_tc<<<gemm_grid, 256>>>(x, Wl0, bl0, Wr0, br0, p_xl, p_xr);
    zero_stats<<<1, 128>>>();
    gat_dst<<<gat_grid, 256>>>(att0, bias0);
    colstats<<<512, 128>>>();
    norm_relu<<<nrm_grid, 256>>>(g0, be0, ms0);

    // ---------- layer 1 ----------
    gemm_dual_tc<<<gemm_grid, 256>>>(p_feat, Wl1, bl1, Wr1, br1, p_xl, p_xr);
    zero_stats<<<1, 128>>>();
    gat_dst<<<gat_grid, 256>>>(att1, bias1);
    colstats<<<512, 128>>>();
    norm_relu<<<nrm_grid, 256>>>(g1, be1, ms1);

    // ---------- MLP head ----------
    mlp_head<<<(N_NODES + 7) / 8, 256>>>(W1, b1, W2, b2, out);
}

// round 14
// speedup vs baseline: 1.6482x; 1.6482x over previous
#include <cuda_runtime.h>
#include <math.h>

#define N_NODES 50000
#define HC 128
#define NHEAD 2
#define CDIM 64
#define E_EDGES 800000
#define ETOT (E_EDGES + N_NODES)
#define NEG_SLOPE 0.2f
#define EPS_GN 1e-5f

typedef unsigned long long ull;

// ---------------- packed f32x2 helpers (sm_100+ FFMA2 path) ------------------
__device__ __forceinline__ ull pack2(float lo, float hi) {
    ull r;
    asm("mov.b64 %0, {%1, %2};" : "=l"(r) : "f"(lo), "f"(hi));
    return r;
}
__device__ __forceinline__ void unpack2(ull v, float& lo, float& hi) {
    asm("mov.b64 {%0, %1}, %2;" : "=f"(lo), "=f"(hi) : "l"(v));
}
__device__ __forceinline__ ull fma2(ull a, ull b, ull c) {
    ull d;
    asm("fma.rn.f32x2 %0, %1, %2, %3;" : "=l"(d) : "l"(a), "l"(b), "l"(c));
    return d;
}

// ---------------- scratch (static device globals; no allocations) ------------
__device__ float d_xl[N_NODES * HC];
__device__ float d_xr[N_NODES * HC];
__device__ float d_feat[N_NODES * HC];
__device__ float d_acc[N_NODES * HC];
__device__ float d_sum[HC];
__device__ float d_sumsq[HC];
// CSR (built once per launch, reused by both layers)
__device__ int d_deg[N_NODES];
__device__ int d_ptr[N_NODES + 1];
__device__ int d_cursor[N_NODES];
__device__ int d_adj[ETOT];

// ------- dual GEMM: Yl = X@Wl+bl, Yr = X@Wr+br (shared X tile) ---------------
// 256 threads, 64 rows/block; FFMA2 inner loops for both outputs.
__global__ __launch_bounds__(256, 2) void gemm_dual(
    const float* __restrict__ X,
    const float* __restrict__ Wl, const float* __restrict__ bl,
    const float* __restrict__ Wr, const float* __restrict__ br,
    float* __restrict__ Yl, float* __restrict__ Yr)
{
    __shared__ float Xs[32][66];     // [kk][row]; width 66 keeps rows 8B-aligned
    __shared__ float Wls[32][128];
    __shared__ float Wrs[32][128];

    const int tid = threadIdx.x;
    const int tx = tid & 31;         // cols tx*4 .. tx*4+3
    const int ty = tid >> 5;         // rows ty*8 .. ty*8+7 (4 packed pairs)
    const int r0 = blockIdx.x * 64;

    ull accl[4][4], accr[4][4];
#pragma unroll
    for (int i = 0; i < 4; i++)
#pragma unroll
        for (int j = 0; j < 4; j++) { accl[i][j] = 0ULL; accr[i][j] = 0ULL; }

    for (int kc = 0; kc < 128; kc += 32) {
        // W chunks: 2 x (32x128) = 2048 float4 total, 8 per thread
#pragma unroll
        for (int i = 0; i < 4; i++) {
            int f = i * 256 + tid;
            int row = f >> 5, c4 = f & 31;
            *(float4*)&Wls[row][c4 * 4] =
                *(const float4*)&Wl[(kc + row) * 128 + c4 * 4];
            *(float4*)&Wrs[row][c4 * 4] =
                *(const float4*)&Wr[(kc + row) * 128 + c4 * 4];
        }
        // X chunk: transpose into k-major Xs[kk][row]
#pragma unroll
        for (int i = 0; i < 2; i++) {
            int f = i * 256 + tid;
            int rr = f >> 3, c4 = f & 7;
            int gr = r0 + rr;
            float4 v = make_float4(0.f, 0.f, 0.f, 0.f);
            if (gr < N_NODES)
                v = *(const float4*)&X[gr * 128 + kc + c4 * 4];
            Xs[c4 * 4 + 0][rr] = v.x;
            Xs[c4 * 4 + 1][rr] = v.y;
            Xs[c4 * 4 + 2][rr] = v.z;
            Xs[c4 * 4 + 3][rr] = v.w;
        }
        __syncthreads();

#pragma unroll 4
        for (int kk = 0; kk < 32; kk++) {
            const ull* arow = (const ull*)&Xs[kk][ty * 8];
            ull a0 = arow[0], a1 = arow[1], a2 = arow[2], a3 = arow[3];

            float4 wv = *(const float4*)&Wls[kk][tx * 4];
            ull w0 = pack2(wv.x, wv.x);
            ull w1 = pack2(wv.y, wv.y);
            ull w2 = pack2(wv.z, wv.z);
            ull w3 = pack2(wv.w, wv.w);
            accl[0][0] = fma2(a0, w0, accl[0][0]);
            accl[0][1] = fma2(a0, w1, accl[0][1]);
            accl[0][2] = fma2(a0, w2, accl[0][2]);
            accl[0][3] = fma2(a0, w3, accl[0][3]);
            accl[1][0] = fma2(a1, w0, accl[1][0]);
            accl[1][1] = fma2(a1, w1, accl[1][1]);
            accl[1][2] = fma2(a1, w2, accl[1][2]);
            accl[1][3] = fma2(a1, w3, accl[1][3]);
            accl[2][0] = fma2(a2, w0, accl[2][0]);
            accl[2][1] = fma2(a2, w1, accl[2][1]);
            accl[2][2] = fma2(a2, w2, accl[2][2]);
            accl[2][3] = fma2(a2, w3, accl[2][3]);
            accl[3][0] = fma2(a3, w0, accl[3][0]);
            accl[3][1] = fma2(a3, w1, accl[3][1]);
            accl[3][2] = fma2(a3, w2, accl[3][2]);
            accl[3][3] = fma2(a3, w3, accl[3][3]);

            wv = *(const float4*)&Wrs[kk][tx * 4];
            w0 = pack2(wv.x, wv.x);
            w1 = pack2(wv.y, wv.y);
            w2 = pack2(wv.z, wv.z);
            w3 = pack2(wv.w, wv.w);
            accr[0][0] = fma2(a0, w0, accr[0][0]);
            accr[0][1] = fma2(a0, w1, accr[0][1]);
            accr[0][2] = fma2(a0, w2, accr[0][2]);
            accr[0][3] = fma2(a0, w3, accr[0][3]);
            accr[1][0] = fma2(a1, w0, accr[1][0]);
            accr[1][1] = fma2(a1, w1, accr[1][1]);
            accr[1][2] = fma2(a1, w2, accr[1][2]);
            accr[1][3] = fma2(a1, w3, accr[1][3]);
            accr[2][0] = fma2(a2, w0, accr[2][0]);
            accr[2][1] = fma2(a2, w1, accr[2][1]);
            accr[2][2] = fma2(a2, w2, accr[2][2]);
            accr[2][3] = fma2(a2, w3, accr[2][3]);
            accr[3][0] = fma2(a3, w0, accr[3][0]);
            accr[3][1] = fma2(a3, w1, accr[3][1]);
            accr[3][2] = fma2(a3, w2, accr[3][2]);
            accr[3][3] = fma2(a3, w3, accr[3][3]);
        }
        __syncthreads();
    }

    float4 bvl = *(const float4*)&bl[tx * 4];
    float4 bvr = *(const float4*)&br[tx * 4];
#pragma unroll
    for (int rp = 0; rp < 4; rp++) {
        int row = r0 + ty * 8 + rp * 2;
        float e0, o0, e1, o1, e2, o2, e3, o3;
        unpack2(accl[rp][0], e0, o0);
        unpack2(accl[rp][1], e1, o1);
        unpack2(accl[rp][2], e2, o2);
        unpack2(accl[rp][3], e3, o3);
        if (row < N_NODES) {
            float4 o = make_float4(e0 + bvl.x, e1 + bvl.y, e2 + bvl.z, e3 + bvl.w);
            *(float4*)&Yl[row * 128 + tx * 4] = o;
        }
        if (row + 1 < N_NODES) {
            float4 o = make_float4(o0 + bvl.x, o1 + bvl.y, o2 + bvl.z, o3 + bvl.w);
            *(float4*)&Yl[(row + 1) * 128 + tx * 4] = o;
        }
        unpack2(accr[rp][0], e0, o0);
        unpack2(accr[rp][1], e1, o1);
        unpack2(accr[rp][2], e2, o2);
        unpack2(accr[rp][3], e3, o3);
        if (row < N_NODES) {
            float4 o = make_float4(e0 + bvr.x, e1 + bvr.y, e2 + bvr.z, e3 + bvr.w);
            *(float4*)&Yr[row * 128 + tx * 4] = o;
        }
        if (row + 1 < N_NODES) {
            float4 o = make_float4(o0 + bvr.x, o1 + bvr.y, o2 + bvr.z, o3 + bvr.w);
            *(float4*)&Yr[(row + 1) * 128 + tx * 4] = o;
        }
    }
}

// ---------------- CSR build --------------------------------------------------
__global__ void csr_deg_init()
{
    int i = blockIdx.x * blockDim.x + threadIdx.x;
    if (i < N_NODES) d_deg[i] = 1;   // self loop counted up front
}

__global__ void csr_count(const int* __restrict__ ei)
{
    int i = blockIdx.x * blockDim.x + threadIdx.x;
    if (i < E_EDGES) atomicAdd(&d_deg[ei[E_EDGES + i]], 1);
}

__global__ __launch_bounds__(1024) void csr_scan()
{
    __shared__ int part[1024];
    const int t = threadIdx.x;
    const int CH = (N_NODES + 1023) / 1024;         // 49
    int beg = t * CH;
    int end = beg + CH; if (end > N_NODES) end = N_NODES;
    if (beg > N_NODES) beg = N_NODES;

    int s = 0;
    for (int i = beg; i < end; i++) s += d_deg[i];
    part[t] = s;
    __syncthreads();
    for (int off = 1; off < 1024; off <<= 1) {
        int v = (t >= off) ? part[t - off] : 0;
        __syncthreads();
        part[t] += v;
        __syncthreads();
    }
    int run = (t == 0) ? 0 : part[t - 1];
    for (int i = beg; i < end; i++) {
        d_ptr[i] = run;
        d_cursor[i] = run;
        run += d_deg[i];
    }
    if (t == 1023) d_ptr[N_NODES] = part[1023];
}

__global__ void csr_scatter(const int* __restrict__ ei)
{
    int i = blockIdx.x * blockDim.x + threadIdx.x;
    if (i >= ETOT) return;
    int s, d;
    if (i < E_EDGES) { s = ei[i]; d = ei[E_EDGES + i]; }
    else             { s = d = i - E_EDGES; }
    int pos = atomicAdd(&d_cursor[d], 1);
    d_adj[pos] = s;
}

// ---------------- fused per-dst GATv2 (no-shift softmax, 2-way unroll) ------
// one warp per dst node; xl gathered once; iterations fully independent.
// block 0 also zeroes the GraphNorm stats (consumed only by later colstats).
__global__ __launch_bounds__(256) void gat_dst(
    const float* __restrict__ att, const float* __restrict__ bias)
{
    if (blockIdx.x == 0 && threadIdx.x < HC) {
        d_sum[threadIdx.x] = 0.f;
        d_sumsq[threadIdx.x] = 0.f;
    }

    const int w = (blockIdx.x * blockDim.x + threadIdx.x) >> 5;
    const int lane = threadIdx.x & 31;
    if (w >= N_NODES) return;

    const int beg = d_ptr[w];
    const int end = d_ptr[w + 1];
    const int ch = lane * 4;

    const float4 xr4 = *(const float4*)&d_xr[(size_t)w * HC + ch];
    const float4 av  = *(const float4*)&att[ch];

    float rsum = 0.f;
    float4 acc = make_float4(0.f, 0.f, 0.f, 0.f);

    int k = beg;
    for (; k + 1 < end; k += 2) {
        int s0 = d_adj[k];
        int s1 = d_adj[k + 1];
        float4 a0 = *(const float4*)&d_xl[(size_t)s0 * HC + ch];
        float4 a1 = *(const float4*)&d_xl[(size_t)s1 * HC + ch];

        float m, p0 = 0.f, p1 = 0.f;
        m = a0.x + xr4.x; m = (m > 0.f) ? m : NEG_SLOPE * m; p0 += m * av.x;
        m = a0.y + xr4.y; m = (m > 0.f) ? m : NEG_SLOPE * m; p0 += m * av.y;
        m = a0.z + xr4.z; m = (m > 0.f) ? m : NEG_SLOPE * m; p0 += m * av.z;
        m = a0.w + xr4.w; m = (m > 0.f) ? m : NEG_SLOPE * m; p0 += m * av.w;
        m = a1.x + xr4.x; m = (m > 0.f) ? m : NEG_SLOPE * m; p1 += m * av.x;
        m = a1.y + xr4.y; m = (m > 0.f) ? m : NEG_SLOPE * m; p1 += m * av.y;
        m = a1.z + xr4.z; m = (m > 0.f) ? m : NEG_SLOPE * m; p1 += m * av.z;
        m = a1.w + xr4.w; m = (m > 0.f) ? m : NEG_SLOPE * m; p1 += m * av.w;

        p0 += __shfl_xor_sync(0xffffffffu, p0, 8, 16);
        p1 += __shfl_xor_sync(0xffffffffu, p1, 8, 16);
        p0 += __shfl_xor_sync(0xffffffffu, p0, 4, 16);
        p1 += __shfl_xor_sync(0xffffffffu, p1, 4, 16);
        p0 += __shfl_xor_sync(0xffffffffu, p0, 2, 16);
        p1 += __shfl_xor_sync(0xffffffffu, p1, 2, 16);
        p0 += __shfl_xor_sync(0xffffffffu, p0, 1, 16);
        p1 += __shfl_xor_sync(0xffffffffu, p1, 1, 16);

        float w0 = __expf(p0);
        float w1 = __expf(p1);
        rsum += w0 + w1;
        acc.x += w0 * a0.x + w1 * a1.x;
        acc.y += w0 * a0.y + w1 * a1.y;
        acc.z += w0 * a0.z + w1 * a1.z;
        acc.w += w0 * a0.w + w1 * a1.w;
    }
    if (k < end) {
        int s0 = d_adj[k];
        float4 a0 = *(const float4*)&d_xl[(size_t)s0 * HC + ch];
        float m, p0 = 0.f;
        m = a0.x + xr4.x; m = (m > 0.f) ? m : NEG_SLOPE * m; p0 += m * av.x;
        m = a0.y + xr4.y; m = (m > 0.f) ? m : NEG_SLOPE * m; p0 += m * av.y;
        m = a0.z + xr4.z; m = (m > 0.f) ? m : NEG_SLOPE * m; p0 += m * av.z;
        m = a0.w + xr4.w; m = (m > 0.f) ? m : NEG_SLOPE * m; p0 += m * av.w;
        p0 += __shfl_xor_sync(0xffffffffu, p0, 8, 16);
        p0 += __shfl_xor_sync(0xffffffffu, p0, 4, 16);
        p0 += __shfl_xor_sync(0xffffffffu, p0, 2, 16);
        p0 += __shfl_xor_sync(0xffffffffu, p0, 1, 16);
        float w0 = __expf(p0);
        rsum += w0;
        acc.x += w0 * a0.x;
        acc.y += w0 * a0.y;
        acc.z += w0 * a0.z;
        acc.w += w0 * a0.w;
    }

    const float invd = 1.f / (rsum + 1e-16f);
    const float4 bv = *(const float4*)&bias[ch];
    float4 o;
    o.x = acc.x * invd + bv.x;
    o.y = acc.y * invd + bv.y;
    o.z = acc.z * invd + bv.z;
    o.w = acc.w * invd + bv.w;
    *(float4*)&d_acc[(size_t)w * HC + ch] = o;
}

// ---------------- GraphNorm stats: sum + sumsq in one pass ------------------
__global__ void colstats()
{
    int c = threadIdx.x;  // 128 threads
    float s = 0.f, q = 0.f;
    for (int r = blockIdx.x; r < N_NODES; r += gridDim.x) {
        float v = d_acc[r * HC + c];
        s += v;
        q += v * v;
    }
    atomicAdd(&d_sum[c], s);
    atomicAdd(&d_sumsq[c], q);
}

__global__ void norm_relu(const float* __restrict__ g,
                          const float* __restrict__ be,
                          const float* __restrict__ ms)
{
    int idx = blockIdx.x * blockDim.x + threadIdx.x;
    if (idx >= N_NODES * HC) return;
    int c = idx & 127;
    float mean = d_sum[c] * (1.f / N_NODES);
    float msq  = d_sumsq[c] * (1.f / N_NODES);
    float mm = ms[c] * mean;
    float var = msq - 2.f * mm * mean + mm * mm;   // E[(x - ms*mean)^2]
    float inv = rsqrtf(var + EPS_GN);
    float y = g[c] * (d_acc[idx] - mm) * inv + be[c];
    d_feat[idx] = (y > 0.f) ? y : 0.f;
}

// ---------------- fused MLP head: relu(feat@W1+b1)@W2+b2 --------------------
__global__ __launch_bounds__(256) void mlp_head(
    const float* __restrict__ W1, const float* __restrict__ b1,
    const float* __restrict__ W2, const float* __restrict__ b2,
    float* __restrict__ out)
{
    __shared__ float W1s[128 * 64];
    __shared__ float W2s[128];
    __shared__ float b1s[64];
    __shared__ float xs[8][128];

    int tid = threadIdx.x;
    for (int i = tid; i < 128 * 64; i += 256) W1s[i] = W1[i];
    if (tid < 128) W2s[tid] = W2[tid];
    if (tid < 64) b1s[tid] = b1[tid];
    __syncthreads();

    int w = tid >> 5, lane = tid & 31;
    float bb0 = b2[0], bb1 = b2[1];

    for (int n = blockIdx.x * 8 + w; n < N_NODES; n += gridDim.x * 8) {
        *(float4*)&xs[w][lane * 4] =
            *(const float4*)&d_feat[(size_t)n * HC + lane * 4];
        __syncwarp();

        float h0 = b1s[lane], h1 = b1s[lane + 32];
#pragma unroll
        for (int k = 0; k < 128; k++) {
            float x = xs[w][k];
            h0 += x * W1s[k * 64 + lane];
            h1 += x * W1s[k * 64 + lane + 32];
        }
        h0 = (h0 > 0.f) ? h0 : 0.f;
        h1 = (h1 > 0.f) ? h1 : 0.f;

        float p0 = h0 * W2s[lane * 2]     + h1 * W2s[(lane + 32) * 2];
        float p1 = h0 * W2s[lane * 2 + 1] + h1 * W2s[(lane + 32) * 2 + 1];
#pragma unroll
        for (int off = 16; off > 0; off >>= 1) {
            p0 += __shfl_down_sync(0xffffffffu, p0, off);
            p1 += __shfl_down_sync(0xffffffffu, p1, off);
        }
        if (lane == 0) {
            out[n * 2]     = p0 + bb0;
            out[n * 2 + 1] = p1 + bb1;
        }
        __syncwarp();
    }
}

// ---------------- driver -----------------------------------------------------
extern "C" void kernel_launch(void* const* d_in, const int* in_sizes, int n_in,
                              void* d_out, int out_size)
{
    const float* x      = (const float*)d_in[0];
    const int*   ei     = (const int*)d_in[1];
    const float* Wl0 = (const float*)d_in[2];
    const float* bl0 = (const float*)d_in[3];
    const float* Wr0 = (const float*)d_in[4];
    const float* br0 = (const float*)d_in[5];
    const float* att0  = (const float*)d_in[6];
    const float* bias0 = (const float*)d_in[7];
    const float* Wl1 = (const float*)d_in[8];
    const float* bl1 = (const float*)d_in[9];
    const float* Wr1 = (const float*)d_in[10];
    const float* br1 = (const float*)d_in[11];
    const float* att1  = (const float*)d_in[12];
    const float* bias1 = (const float*)d_in[13];
    const float* g0  = (const float*)d_in[14];
    const float* be0 = (const float*)d_in[15];
    const float* ms0 = (const float*)d_in[16];
    const float* g1  = (const float*)d_in[17];
    const float* be1 = (const float*)d_in[18];
    const float* ms1 = (const float*)d_in[19];
    const float* W1 = (const float*)d_in[20];
    const float* b1 = (const float*)d_in[21];
    const float* W2 = (const float*)d_in[22];
    const float* b2 = (const float*)d_in[23];
    float* out = (float*)d_out;

    float *p_xl, *p_xr, *p_feat;
    cudaGetSymbolAddress((void**)&p_xl,   d_xl);
    cudaGetSymbolAddress((void**)&p_xr,   d_xr);
    cudaGetSymbolAddress((void**)&p_feat, d_feat);

    const int gemm_grid = (N_NODES + 63) / 64;
    const int nrm_grid  = (N_NODES * HC + 255) / 256;
    const int gat_grid  = (N_NODES * 32 + 255) / 256;   // warp per dst

    // ---------- CSR build + layer-0 GEMM ----------
    // gemm_dual is CSR-independent; placed 4th so the profiler (which captures
    // the 4th launch) lands on it. csr_scatter only needs csr_scan.
    csr_deg_init<<<(N_NODES + 255) / 256, 256>>>();
    csr_count<<<(E_EDGES + 255) / 256, 256>>>(ei);
    csr_scan<<<1, 1024>>>();
    gemm_dual<<<gemm_grid, 256>>>(x, Wl0, bl0, Wr0, br0, p_xl, p_xr);  // #4
    csr_scatter<<<(ETOT + 255) / 256, 256>>>(ei);

    // ---------- layer 0 ----------
    gat_dst<<<gat_grid, 256>>>(att0, bias0);
    colstats<<<512, 128>>>();
    norm_relu<<<nrm_grid, 256>>>(g0, be0, ms0);

    // ---------- layer 1 ----------
    gemm_dual<<<gemm_grid, 256>>>(p_feat, Wl1, bl1, Wr1, br1, p_xl, p_xr);
    gat_dst<<<gat_grid, 256>>>(att1, bias1);
    colstats<<<512, 128>>>();
    norm_relu<<<nrm_grid, 256>>>(g1, be1, ms1);

    // ---------- MLP head ----------
    mlp_head<<<1480, 256>>>(W1, b1, W2, b2, out);
}

// round 15
// speedup vs baseline: 1.7185x; 1.0427x over previous
#include <cuda_runtime.h>
#include <math.h>

#define N_NODES 50000
#define HC 128
#define NHEAD 2
#define CDIM 64
#define E_EDGES 800000
#define ETOT (E_EDGES + N_NODES)
#define NEG_SLOPE 0.2f
#define EPS_GN 1e-5f

typedef unsigned long long ull;

// ---------------- packed f32x2 helpers (sm_100+ FFMA2 path) ------------------
__device__ __forceinline__ ull pack2(float lo, float hi) {
    ull r;
    asm("mov.b64 %0, {%1, %2};" : "=l"(r) : "f"(lo), "f"(hi));
    return r;
}
__device__ __forceinline__ void unpack2(ull v, float& lo, float& hi) {
    asm("mov.b64 {%0, %1}, %2;" : "=f"(lo), "=f"(hi) : "l"(v));
}
__device__ __forceinline__ ull fma2(ull a, ull b, ull c) {
    ull d;
    asm("fma.rn.f32x2 %0, %1, %2, %3;" : "=l"(d) : "l"(a), "l"(b), "l"(c));
    return d;
}

// ---------------- scratch (static device globals; no allocations) ------------
__device__ float d_xl[N_NODES * HC];
__device__ float d_xr[N_NODES * HC];
__device__ float d_feat[N_NODES * HC];
__device__ float d_acc[N_NODES * HC];
__device__ float d_sum[HC];
__device__ float d_sumsq[HC];
// CSR (built once per launch, reused by both layers).
// d_deg is zero at module load and re-zeroed by csr_scan each run.
__device__ int d_deg[N_NODES];
__device__ int d_ptr[N_NODES + 1];
__device__ int d_cursor[N_NODES];
__device__ int d_adj[ETOT];

// ------- GEMM: Y = X@W + b, one W per block (blockIdx.y: 0=Wl, 1=Wr) --------
// 256 threads, 64 rows x 128 cols per block; FFMA2 inner loop.
// Optional prologue: count edge in-degrees (overlaps GEMM LDG latency).
__global__ __launch_bounds__(256, 3) void gemm_fused(
    const float* __restrict__ X,
    const float* __restrict__ Wl, const float* __restrict__ bl,
    const float* __restrict__ Wr, const float* __restrict__ br,
    float* __restrict__ Yl, float* __restrict__ Yr,
    const int* __restrict__ ei)          // non-null => also count degrees
{
    __shared__ float Xs[32][66];     // [kk][row]; width 66 keeps rows 8B-aligned
    __shared__ float Ws[32][128];

    const int tid = threadIdx.x;

    if (ei) {
        int gtid = (blockIdx.y * gridDim.x + blockIdx.x) * 256 + tid;
        int total = gridDim.x * 2 * 256;
        for (int e = gtid; e < E_EDGES; e += total)
            atomicAdd(&d_deg[ei[E_EDGES + e]], 1);
    }

    const float* W    = blockIdx.y ? Wr : Wl;
    const float* bias = blockIdx.y ? br : bl;
    float*       Y    = blockIdx.y ? Yr : Yl;

    const int tx = tid & 31;         // cols tx*4 .. tx*4+3
    const int ty = tid >> 5;         // rows ty*8 .. ty*8+7 (4 packed pairs)
    const int r0 = blockIdx.x * 64;

    ull acc[4][4];
#pragma unroll
    for (int i = 0; i < 4; i++)
#pragma unroll
        for (int j = 0; j < 4; j++) acc[i][j] = 0ULL;

    for (int kc = 0; kc < 128; kc += 32) {
        // W chunk: 32x128 = 1024 float4, 4 per thread
#pragma unroll
        for (int i = 0; i < 4; i++) {
            int f = i * 256 + tid;
            int row = f >> 5, c4 = f & 31;
            *(float4*)&Ws[row][c4 * 4] =
                *(const float4*)&W[(kc + row) * 128 + c4 * 4];
        }
        // X chunk: transpose into k-major Xs[kk][row]
#pragma unroll
        for (int i = 0; i < 2; i++) {
            int f = i * 256 + tid;
            int rr = f >> 3, c4 = f & 7;
            int gr = r0 + rr;
            float4 v = make_float4(0.f, 0.f, 0.f, 0.f);
            if (gr < N_NODES)
                v = *(const float4*)&X[gr * 128 + kc + c4 * 4];
            Xs[c4 * 4 + 0][rr] = v.x;
            Xs[c4 * 4 + 1][rr] = v.y;
            Xs[c4 * 4 + 2][rr] = v.z;
            Xs[c4 * 4 + 3][rr] = v.w;
        }
        __syncthreads();

#pragma unroll 8
        for (int kk = 0; kk < 32; kk++) {
            const ull* arow = (const ull*)&Xs[kk][ty * 8];
            ull a0 = arow[0], a1 = arow[1], a2 = arow[2], a3 = arow[3];

            float4 wv = *(const float4*)&Ws[kk][tx * 4];
            ull w0 = pack2(wv.x, wv.x);
            ull w1 = pack2(wv.y, wv.y);
            ull w2 = pack2(wv.z, wv.z);
            ull w3 = pack2(wv.w, wv.w);
            acc[0][0] = fma2(a0, w0, acc[0][0]);
            acc[0][1] = fma2(a0, w1, acc[0][1]);
            acc[0][2] = fma2(a0, w2, acc[0][2]);
            acc[0][3] = fma2(a0, w3, acc[0][3]);
            acc[1][0] = fma2(a1, w0, acc[1][0]);
            acc[1][1] = fma2(a1, w1, acc[1][1]);
            acc[1][2] = fma2(a1, w2, acc[1][2]);
            acc[1][3] = fma2(a1, w3, acc[1][3]);
            acc[2][0] = fma2(a2, w0, acc[2][0]);
            acc[2][1] = fma2(a2, w1, acc[2][1]);
            acc[2][2] = fma2(a2, w2, acc[2][2]);
            acc[2][3] = fma2(a2, w3, acc[2][3]);
            acc[3][0] = fma2(a3, w0, acc[3][0]);
            acc[3][1] = fma2(a3, w1, acc[3][1]);
            acc[3][2] = fma2(a3, w2, acc[3][2]);
            acc[3][3] = fma2(a3, w3, acc[3][3]);
        }
        __syncthreads();
    }

    float4 bv = *(const float4*)&bias[tx * 4];
#pragma unroll
    for (int rp = 0; rp < 4; rp++) {
        int row = r0 + ty * 8 + rp * 2;
        float e0, o0, e1, o1, e2, o2, e3, o3;
        unpack2(acc[rp][0], e0, o0);
        unpack2(acc[rp][1], e1, o1);
        unpack2(acc[rp][2], e2, o2);
        unpack2(acc[rp][3], e3, o3);
        if (row < N_NODES) {
            float4 o = make_float4(e0 + bv.x, e1 + bv.y, e2 + bv.z, e3 + bv.w);
            *(float4*)&Y[row * 128 + tx * 4] = o;
        }
        if (row + 1 < N_NODES) {
            float4 o = make_float4(o0 + bv.x, o1 + bv.y, o2 + bv.z, o3 + bv.w);
            *(float4*)&Y[(row + 1) * 128 + tx * 4] = o;
        }
    }
}

// ---------------- CSR scan: ptr from deg+1 (self loop); resets deg ----------
__global__ __launch_bounds__(1024) void csr_scan()
{
    __shared__ int part[1024];
    const int t = threadIdx.x;
    const int CH = (N_NODES + 1023) / 1024;         // 49
    int beg = t * CH;
    int end = beg + CH; if (end > N_NODES) end = N_NODES;
    if (beg > N_NODES) beg = N_NODES;

    int s = 0;
    for (int i = beg; i < end; i++) s += d_deg[i] + 1;
    part[t] = s;
    __syncthreads();
    for (int off = 1; off < 1024; off <<= 1) {
        int v = (t >= off) ? part[t - off] : 0;
        __syncthreads();
        part[t] += v;
        __syncthreads();
    }
    int run = (t == 0) ? 0 : part[t - 1];
    for (int i = beg; i < end; i++) {
        int dv = d_deg[i] + 1;
        d_ptr[i] = run;
        d_cursor[i] = run;
        d_deg[i] = 0;               // reset for the next replay (deterministic)
        run += dv;
    }
    if (t == 1023) d_ptr[N_NODES] = part[1023];
}

__global__ void csr_scatter(const int* __restrict__ ei)
{
    int i = blockIdx.x * blockDim.x + threadIdx.x;
    if (i >= ETOT) return;
    int s, d;
    if (i < E_EDGES) { s = ei[i]; d = ei[E_EDGES + i]; }
    else             { s = d = i - E_EDGES; }
    int pos = atomicAdd(&d_cursor[d], 1);
    d_adj[pos] = s;
}

// ---------------- fused per-dst GATv2 (no-shift softmax, 2-way unroll) ------
// one warp per dst node; xl gathered once; iterations fully independent.
// block 0 also zeroes the GraphNorm stats (consumed only by later colstats).
__global__ __launch_bounds__(256) void gat_dst(
    const float* __restrict__ att, const float* __restrict__ bias)
{
    if (blockIdx.x == 0 && threadIdx.x < HC) {
        d_sum[threadIdx.x] = 0.f;
        d_sumsq[threadIdx.x] = 0.f;
    }

    const int w = (blockIdx.x * blockDim.x + threadIdx.x) >> 5;
    const int lane = threadIdx.x & 31;
    if (w >= N_NODES) return;

    const int beg = d_ptr[w];
    const int end = d_ptr[w + 1];
    const int ch = lane * 4;

    const float4 xr4 = *(const float4*)&d_xr[(size_t)w * HC + ch];
    const float4 av  = *(const float4*)&att[ch];

    float rsum = 0.f;
    float4 acc = make_float4(0.f, 0.f, 0.f, 0.f);

    int k = beg;
    for (; k + 1 < end; k += 2) {
        int s0 = d_adj[k];
        int s1 = d_adj[k + 1];
        float4 a0 = *(const float4*)&d_xl[(size_t)s0 * HC + ch];
        float4 a1 = *(const float4*)&d_xl[(size_t)s1 * HC + ch];

        float m, p0 = 0.f, p1 = 0.f;
        m = a0.x + xr4.x; m = (m > 0.f) ? m : NEG_SLOPE * m; p0 += m * av.x;
        m = a0.y + xr4.y; m = (m > 0.f) ? m : NEG_SLOPE * m; p0 += m * av.y;
        m = a0.z + xr4.z; m = (m > 0.f) ? m : NEG_SLOPE * m; p0 += m * av.z;
        m = a0.w + xr4.w; m = (m > 0.f) ? m : NEG_SLOPE * m; p0 += m * av.w;
        m = a1.x + xr4.x; m = (m > 0.f) ? m : NEG_SLOPE * m; p1 += m * av.x;
        m = a1.y + xr4.y; m = (m > 0.f) ? m : NEG_SLOPE * m; p1 += m * av.y;
        m = a1.z + xr4.z; m = (m > 0.f) ? m : NEG_SLOPE * m; p1 += m * av.z;
        m = a1.w + xr4.w; m = (m > 0.f) ? m : NEG_SLOPE * m; p1 += m * av.w;

        p0 += __shfl_xor_sync(0xffffffffu, p0, 8, 16);
        p1 += __shfl_xor_sync(0xffffffffu, p1, 8, 16);
        p0 += __shfl_xor_sync(0xffffffffu, p0, 4, 16);
        p1 += __shfl_xor_sync(0xffffffffu, p1, 4, 16);
        p0 += __shfl_xor_sync(0xffffffffu, p0, 2, 16);
        p1 += __shfl_xor_sync(0xffffffffu, p1, 2, 16);
        p0 += __shfl_xor_sync(0xffffffffu, p0, 1, 16);
        p1 += __shfl_xor_sync(0xffffffffu, p1, 1, 16);

        float w0 = __expf(p0);
        float w1 = __expf(p1);
        rsum += w0 + w1;
        acc.x += w0 * a0.x + w1 * a1.x;
        acc.y += w0 * a0.y + w1 * a1.y;
        acc.z += w0 * a0.z + w1 * a1.z;
        acc.w += w0 * a0.w + w1 * a1.w;
    }
    if (k < end) {
        int s0 = d_adj[k];
        float4 a0 = *(const float4*)&d_xl[(size_t)s0 * HC + ch];
        float m, p0 = 0.f;
        m = a0.x + xr4.x; m = (m > 0.f) ? m : NEG_SLOPE * m; p0 += m * av.x;
        m = a0.y + xr4.y; m = (m > 0.f) ? m : NEG_SLOPE * m; p0 += m * av.y;
        m = a0.z + xr4.z; m = (m > 0.f) ? m : NEG_SLOPE * m; p0 += m * av.z;
        m = a0.w + xr4.w; m = (m > 0.f) ? m : NEG_SLOPE * m; p0 += m * av.w;
        p0 += __shfl_xor_sync(0xffffffffu, p0, 8, 16);
        p0 += __shfl_xor_sync(0xffffffffu, p0, 4, 16);
        p0 += __shfl_xor_sync(0xffffffffu, p0, 2, 16);
        p0 += __shfl_xor_sync(0xffffffffu, p0, 1, 16);
        float w0 = __expf(p0);
        rsum += w0;
        acc.x += w0 * a0.x;
        acc.y += w0 * a0.y;
        acc.z += w0 * a0.z;
        acc.w += w0 * a0.w;
    }

    const float invd = 1.f / (rsum + 1e-16f);
    const float4 bv = *(const float4*)&bias[ch];
    float4 o;
    o.x = acc.x * invd + bv.x;
    o.y = acc.y * invd + bv.y;
    o.z = acc.z * invd + bv.z;
    o.w = acc.w * invd + bv.w;
    *(float4*)&d_acc[(size_t)w * HC + ch] = o;
}

// ---------------- GraphNorm stats: sum + sumsq in one pass ------------------
__global__ void colstats()
{
    int c = threadIdx.x;  // 128 threads
    float s = 0.f, q = 0.f;
    for (int r = blockIdx.x; r < N_NODES; r += gridDim.x) {
        float v = d_acc[r * HC + c];
        s += v;
        q += v * v;
    }
    atomicAdd(&d_sum[c], s);
    atomicAdd(&d_sumsq[c], q);
}

__global__ void norm_relu(const float* __restrict__ g,
                          const float* __restrict__ be,
                          const float* __restrict__ ms)
{
    int idx = blockIdx.x * blockDim.x + threadIdx.x;
    if (idx >= N_NODES * HC) return;
    int c = idx & 127;
    float mean = d_sum[c] * (1.f / N_NODES);
    float msq  = d_sumsq[c] * (1.f / N_NODES);
    float mm = ms[c] * mean;
    float var = msq - 2.f * mm * mean + mm * mm;   // E[(x - ms*mean)^2]
    float inv = rsqrtf(var + EPS_GN);
    float y = g[c] * (d_acc[idx] - mm) * inv + be[c];
    d_feat[idx] = (y > 0.f) ? y : 0.f;
}

// ---------------- fused MLP head: relu(feat@W1+b1)@W2+b2 --------------------
__global__ __launch_bounds__(256) void mlp_head(
    const float* __restrict__ W1, const float* __restrict__ b1,
    const float* __restrict__ W2, const float* __restrict__ b2,
    float* __restrict__ out)
{
    __shared__ float W1s[128 * 64];
    __shared__ float W2s[128];
    __shared__ float b1s[64];
    __shared__ float xs[8][128];

    int tid = threadIdx.x;
    for (int i = tid; i < 128 * 64; i += 256) W1s[i] = W1[i];
    if (tid < 128) W2s[tid] = W2[tid];
    if (tid < 64) b1s[tid] = b1[tid];
    __syncthreads();

    int w = tid >> 5, lane = tid & 31;
    float bb0 = b2[0], bb1 = b2[1];

    for (int n = blockIdx.x * 8 + w; n < N_NODES; n += gridDim.x * 8) {
        *(float4*)&xs[w][lane * 4] =
            *(const float4*)&d_feat[(size_t)n * HC + lane * 4];
        __syncwarp();

        float h0 = b1s[lane], h1 = b1s[lane + 32];
#pragma unroll
        for (int k = 0; k < 128; k++) {
            float x = xs[w][k];
            h0 += x * W1s[k * 64 + lane];
            h1 += x * W1s[k * 64 + lane + 32];
        }
        h0 = (h0 > 0.f) ? h0 : 0.f;
        h1 = (h1 > 0.f) ? h1 : 0.f;

        float p0 = h0 * W2s[lane * 2]     + h1 * W2s[(lane + 32) * 2];
        float p1 = h0 * W2s[lane * 2 + 1] + h1 * W2s[(lane + 32) * 2 + 1];
#pragma unroll
        for (int off = 16; off > 0; off >>= 1) {
            p0 += __shfl_down_sync(0xffffffffu, p0, off);
            p1 += __shfl_down_sync(0xffffffffu, p1, off);
        }
        if (lane == 0) {
            out[n * 2]     = p0 + bb0;
            out[n * 2 + 1] = p1 + bb1;
        }
        __syncwarp();
    }
}

// ---------------- driver -----------------------------------------------------
extern "C" void kernel_launch(void* const* d_in, const int* in_sizes, int n_in,
                              void* d_out, int out_size)
{
    const float* x      = (const float*)d_in[0];
    const int*   ei     = (const int*)d_in[1];
    const float* Wl0 = (const float*)d_in[2];
    const float* bl0 = (const float*)d_in[3];
    const float* Wr0 = (const float*)d_in[4];
    const float* br0 = (const float*)d_in[5];
    const float* att0  = (const float*)d_in[6];
    const float* bias0 = (const float*)d_in[7];
    const float* Wl1 = (const float*)d_in[8];
    const float* bl1 = (const float*)d_in[9];
    const float* Wr1 = (const float*)d_in[10];
    const float* br1 = (const float*)d_in[11];
    const float* att1  = (const float*)d_in[12];
    const float* bias1 = (const float*)d_in[13];
    const float* g0  = (const float*)d_in[14];
    const float* be0 = (const float*)d_in[15];
    const float* ms0 = (const float*)d_in[16];
    const float* g1  = (const float*)d_in[17];
    const float* be1 = (const float*)d_in[18];
    const float* ms1 = (const float*)d_in[19];
    const float* W1 = (const float*)d_in[20];
    const float* b1 = (const float*)d_in[21];
    const float* W2 = (const float*)d_in[22];
    const float* b2 = (const float*)d_in[23];
    float* out = (float*)d_out;

    float *p_xl, *p_xr, *p_feat;
    cudaGetSymbolAddress((void**)&p_xl,   d_xl);
    cudaGetSymbolAddress((void**)&p_xr,   d_xr);
    cudaGetSymbolAddress((void**)&p_feat, d_feat);

    const dim3 gemm_grid((N_NODES + 63) / 64, 2);       // (782, 2)
    const int nrm_grid  = (N_NODES * HC + 255) / 256;
    const int gat_grid  = (N_NODES * 32 + 255) / 256;   // warp per dst

    // #1: layer-0 GEMM + fused degree count (d_deg starts zero each run)
    gemm_fused<<<gemm_grid, 256>>>(x, Wl0, bl0, Wr0, br0, p_xl, p_xr, ei);
    // #2: prefix sum (adds +1 self loop, resets d_deg for next replay)
    csr_scan<<<1, 1024>>>();
    // #3: adjacency scatter
    csr_scatter<<<(ETOT + 255) / 256, 256>>>(ei);
    // #4: layer-0 GAT  <-- profiler lands here
    gat_dst<<<gat_grid, 256>>>(att0, bias0);
    colstats<<<512, 128>>>();
    norm_relu<<<nrm_grid, 256>>>(g0, be0, ms0);

    // ---------- layer 1 ----------
    gemm_fused<<<gemm_grid, 256>>>(p_feat, Wl1, bl1, Wr1, br1, p_xl, p_xr,
                                   (const int*)nullptr);
    gat_dst<<<gat_grid, 256>>>(att1, bias1);
    colstats<<<512, 128>>>();
    norm_relu<<<nrm_grid, 256>>>(g1, be1, ms1);

    // ---------- MLP head ----------
    mlp_head<<<(N_NODES + 7) / 8, 256>>>(W1, b1, W2, b2, out);
}

// round 16
// speedup vs baseline: 2.0139x; 1.1719x over previous
#include <cuda_runtime.h>
#include <math.h>

#define N_NODES 50000
#define HC 128
#define NHEAD 2
#define CDIM 64
#define E_EDGES 800000
#define ETOT (E_EDGES + N_NODES)
#define NEG_SLOPE 0.2f
#define EPS_GN 1e-5f
#define INV_N (1.f / N_NODES)

typedef unsigned long long ull;

// ---------------- packed f32x2 helpers (sm_100+ FFMA2 path) ------------------
__device__ __forceinline__ ull pack2(float lo, float hi) {
    ull r;
    asm("mov.b64 %0, {%1, %2};" : "=l"(r) : "f"(lo), "f"(hi));
    return r;
}
__device__ __forceinline__ void unpack2(ull v, float& lo, float& hi) {
    asm("mov.b64 {%0, %1}, %2;" : "=f"(lo), "=f"(hi) : "l"(v));
}
__device__ __forceinline__ ull fma2(ull a, ull b, ull c) {
    ull d;
    asm("fma.rn.f32x2 %0, %1, %2, %3;" : "=l"(d) : "l"(a), "l"(b), "l"(c));
    return d;
}

// ---------------- scratch (static device globals; no allocations) ------------
__device__ float d_xl[N_NODES * HC];
__device__ float d_xr[N_NODES * HC];
__device__ float d_acc[N_NODES * HC];
__device__ float d_sumF[2 * HC];      // per-layer GraphNorm column sums
__device__ float d_sumsqF[2 * HC];
// CSR (built once per launch, reused by both layers).
// d_deg is zero at module load and re-zeroed by csr_scan each run.
__device__ int d_deg[N_NODES];
__device__ int d_ptr[N_NODES + 1];
__device__ int d_cursor[N_NODES];
__device__ int d_adj[ETOT];

// ------- GEMM: Y = X@W + b, one W per block (blockIdx.y: 0=Wl, 1=Wr) --------
// 256 threads, 64 rows x 128 cols; FFMA2 inner loop.
// Optional prologue A: count edge in-degrees (layer 0, overlaps GEMM LDG).
// Optional prologue B: per-column GraphNorm+ReLU applied to X on load
// (layer 1 reads d_acc directly; norm params + stats offset supplied).
__global__ __launch_bounds__(256, 3) void gemm_fused(
    const float* __restrict__ X,
    const float* __restrict__ Wl, const float* __restrict__ bl,
    const float* __restrict__ Wr, const float* __restrict__ br,
    float* __restrict__ Yl, float* __restrict__ Yr,
    const int* __restrict__ ei,                 // non-null => count degrees
    const float* __restrict__ gamma,            // non-null => normalize X
    const float* __restrict__ beta,
    const float* __restrict__ mscale,
    int statOff)
{
    __shared__ float Xs[32][66];     // [kk][row]; width 66 keeps rows 8B-aligned
    __shared__ float Ws[32][128];
    __shared__ float As[128], Bs[128];

    const int tid = threadIdx.x;

    if (ei) {
        int gtid = (blockIdx.y * gridDim.x + blockIdx.x) * 256 + tid;
        int total = gridDim.x * 2 * 256;
        for (int e = gtid; e < E_EDGES; e += total)
            atomicAdd(&d_deg[ei[E_EDGES + e]], 1);
    }
    if (gamma) {
        if (tid < 128) {
            int c = tid;
            float mean = d_sumF[statOff + c] * INV_N;
            float msq  = d_sumsqF[statOff + c] * INV_N;
            float mm   = mscale[c] * mean;
            float var  = msq - 2.f * mm * mean + mm * mm;
            float inv  = rsqrtf(var + EPS_GN);
            float A    = gamma[c] * inv;
            As[c] = A;
            Bs[c] = beta[c] - A * mm;
        }
        __syncthreads();
    }

    const float* W    = blockIdx.y ? Wr : Wl;
    const float* bias = blockIdx.y ? br : bl;
    float*       Y    = blockIdx.y ? Yr : Yl;

    const int tx = tid & 31;         // cols tx*4 .. tx*4+3
    const int ty = tid >> 5;         // rows ty*8 .. ty*8+7 (4 packed pairs)
    const int r0 = blockIdx.x * 64;

    ull acc[4][4];
#pragma unroll
    for (int i = 0; i < 4; i++)
#pragma unroll
        for (int j = 0; j < 4; j++) acc[i][j] = 0ULL;

    for (int kc = 0; kc < 128; kc += 32) {
        // W chunk: 32x128 = 1024 float4, 4 per thread
#pragma unroll
        for (int i = 0; i < 4; i++) {
            int f = i * 256 + tid;
            int row = f >> 5, c4 = f & 31;
            *(float4*)&Ws[row][c4 * 4] =
                *(const float4*)&W[(kc + row) * 128 + c4 * 4];
        }
        // X chunk: transpose into k-major Xs[kk][row]; optional norm+relu
#pragma unroll
        for (int i = 0; i < 2; i++) {
            int f = i * 256 + tid;
            int rr = f >> 3, c4 = f & 7;
            int gr = r0 + rr;
            float4 v = make_float4(0.f, 0.f, 0.f, 0.f);
            if (gr < N_NODES)
                v = *(const float4*)&X[gr * 128 + kc + c4 * 4];
            if (gamma) {
                int c0 = kc + c4 * 4;
                v.x = fmaxf(As[c0 + 0] * v.x + Bs[c0 + 0], 0.f);
                v.y = fmaxf(As[c0 + 1] * v.y + Bs[c0 + 1], 0.f);
                v.z = fmaxf(As[c0 + 2] * v.z + Bs[c0 + 2], 0.f);
                v.w = fmaxf(As[c0 + 3] * v.w + Bs[c0 + 3], 0.f);
            }
            Xs[c4 * 4 + 0][rr] = v.x;
            Xs[c4 * 4 + 1][rr] = v.y;
            Xs[c4 * 4 + 2][rr] = v.z;
            Xs[c4 * 4 + 3][rr] = v.w;
        }
        __syncthreads();

#pragma unroll 8
        for (int kk = 0; kk < 32; kk++) {
            const ull* arow = (const ull*)&Xs[kk][ty * 8];
            ull a0 = arow[0], a1 = arow[1], a2 = arow[2], a3 = arow[3];

            float4 wv = *(const float4*)&Ws[kk][tx * 4];
            ull w0 = pack2(wv.x, wv.x);
            ull w1 = pack2(wv.y, wv.y);
            ull w2 = pack2(wv.z, wv.z);
            ull w3 = pack2(wv.w, wv.w);
            acc[0][0] = fma2(a0, w0, acc[0][0]);
            acc[0][1] = fma2(a0, w1, acc[0][1]);
            acc[0][2] = fma2(a0, w2, acc[0][2]);
            acc[0][3] = fma2(a0, w3, acc[0][3]);
            acc[1][0] = fma2(a1, w0, acc[1][0]);
            acc[1][1] = fma2(a1, w1, acc[1][1]);
            acc[1][2] = fma2(a1, w2, acc[1][2]);
            acc[1][3] = fma2(a1, w3, acc[1][3]);
            acc[2][0] = fma2(a2, w0, acc[2][0]);
            acc[2][1] = fma2(a2, w1, acc[2][1]);
            acc[2][2] = fma2(a2, w2, acc[2][2]);
            acc[2][3] = fma2(a2, w3, acc[2][3]);
            acc[3][0] = fma2(a3, w0, acc[3][0]);
            acc[3][1] = fma2(a3, w1, acc[3][1]);
            acc[3][2] = fma2(a3, w2, acc[3][2]);
            acc[3][3] = fma2(a3, w3, acc[3][3]);
        }
        __syncthreads();
    }

    float4 bv = *(const float4*)&bias[tx * 4];
#pragma unroll
    for (int rp = 0; rp < 4; rp++) {
        int row = r0 + ty * 8 + rp * 2;
        float e0, o0, e1, o1, e2, o2, e3, o3;
        unpack2(acc[rp][0], e0, o0);
        unpack2(acc[rp][1], e1, o1);
        unpack2(acc[rp][2], e2, o2);
        unpack2(acc[rp][3], e3, o3);
        if (row < N_NODES) {
            float4 o = make_float4(e0 + bv.x, e1 + bv.y, e2 + bv.z, e3 + bv.w);
            *(float4*)&Y[row * 128 + tx * 4] = o;
        }
        if (row + 1 < N_NODES) {
            float4 o = make_float4(o0 + bv.x, o1 + bv.y, o2 + bv.z, o3 + bv.w);
            *(float4*)&Y[(row + 1) * 128 + tx * 4] = o;
        }
    }
}

// ---------------- CSR scan: ptr from deg+1 (self loop); resets deg ----------
__global__ __launch_bounds__(1024) void csr_scan()
{
    __shared__ int part[1024];
    const int t = threadIdx.x;
    const int CH = (N_NODES + 1023) / 1024;         // 49
    int beg = t * CH;
    int end = beg + CH; if (end > N_NODES) end = N_NODES;
    if (beg > N_NODES) beg = N_NODES;

    int s = 0;
    for (int i = beg; i < end; i++) s += d_deg[i] + 1;
    part[t] = s;
    __syncthreads();
    for (int off = 1; off < 1024; off <<= 1) {
        int v = (t >= off) ? part[t - off] : 0;
        __syncthreads();
        part[t] += v;
        __syncthreads();
    }
    int run = (t == 0) ? 0 : part[t - 1];
    for (int i = beg; i < end; i++) {
        int dv = d_deg[i] + 1;
        d_ptr[i] = run;
        d_cursor[i] = run;
        d_deg[i] = 0;               // reset for the next replay (deterministic)
        run += dv;
    }
    if (t == 1023) d_ptr[N_NODES] = part[1023];
}

// scatter adjacency; block 0 also zeroes both layers' GraphNorm stats
// (safe: stats are only touched later, by gat_dst)
__global__ void csr_scatter(const int* __restrict__ ei)
{
    if (blockIdx.x == 0 && threadIdx.x < 2 * HC) {
        d_sumF[threadIdx.x] = 0.f;
        d_sumsqF[threadIdx.x] = 0.f;
    }
    int i = blockIdx.x * blockDim.x + threadIdx.x;
    if (i >= ETOT) return;
    int s, d;
    if (i < E_EDGES) { s = ei[i]; d = ei[E_EDGES + i]; }
    else             { s = d = i - E_EDGES; }
    int pos = atomicAdd(&d_cursor[d], 1);
    d_adj[pos] = s;
}

// ---------------- fused per-dst GATv2 + GraphNorm column stats --------------
// one warp per dst node (grid is EXACTLY 50000 warps = 6250 blocks x 8);
// no-shift softmax, 2-way unroll, xl gathered once, no per-edge atomics.
// Epilogue: block-level smem reduction of output columns -> stats atomics.
__global__ __launch_bounds__(256) void gat_dst(
    const float* __restrict__ att, const float* __restrict__ bias,
    int statOff)
{
    __shared__ float red[8][128];

    const int w = (blockIdx.x * blockDim.x + threadIdx.x) >> 5;
    const int wwarp = threadIdx.x >> 5;
    const int lane = threadIdx.x & 31;

    const int beg = d_ptr[w];
    const int end = d_ptr[w + 1];
    const int ch = lane * 4;

    const float4 xr4 = *(const float4*)&d_xr[(size_t)w * HC + ch];
    const float4 av  = *(const float4*)&att[ch];

    float rsum = 0.f;
    float4 acc = make_float4(0.f, 0.f, 0.f, 0.f);

    int k = beg;
    for (; k + 1 < end; k += 2) {
        int s0 = d_adj[k];
        int s1 = d_adj[k + 1];
        float4 a0 = *(const float4*)&d_xl[(size_t)s0 * HC + ch];
        float4 a1 = *(const float4*)&d_xl[(size_t)s1 * HC + ch];

        float m, p0 = 0.f, p1 = 0.f;
        m = a0.x + xr4.x; m = (m > 0.f) ? m : NEG_SLOPE * m; p0 += m * av.x;
        m = a0.y + xr4.y; m = (m > 0.f) ? m : NEG_SLOPE * m; p0 += m * av.y;
        m = a0.z + xr4.z; m = (m > 0.f) ? m : NEG_SLOPE * m; p0 += m * av.z;
        m = a0.w + xr4.w; m = (m > 0.f) ? m : NEG_SLOPE * m; p0 += m * av.w;
        m = a1.x + xr4.x; m = (m > 0.f) ? m : NEG_SLOPE * m; p1 += m * av.x;
        m = a1.y + xr4.y; m = (m > 0.f) ? m : NEG_SLOPE * m; p1 += m * av.y;
        m = a1.z + xr4.z; m = (m > 0.f) ? m : NEG_SLOPE * m; p1 += m * av.z;
        m = a1.w + xr4.w; m = (m > 0.f) ? m : NEG_SLOPE * m; p1 += m * av.w;

        p0 += __shfl_xor_sync(0xffffffffu, p0, 8, 16);
        p1 += __shfl_xor_sync(0xffffffffu, p1, 8, 16);
        p0 += __shfl_xor_sync(0xffffffffu, p0, 4, 16);
        p1 += __shfl_xor_sync(0xffffffffu, p1, 4, 16);
        p0 += __shfl_xor_sync(0xffffffffu, p0, 2, 16);
        p1 += __shfl_xor_sync(0xffffffffu, p1, 2, 16);
        p0 += __shfl_xor_sync(0xffffffffu, p0, 1, 16);
        p1 += __shfl_xor_sync(0xffffffffu, p1, 1, 16);

        float w0 = __expf(p0);
        float w1 = __expf(p1);
        rsum += w0 + w1;
        acc.x += w0 * a0.x + w1 * a1.x;
        acc.y += w0 * a0.y + w1 * a1.y;
        acc.z += w0 * a0.z + w1 * a1.z;
        acc.w += w0 * a0.w + w1 * a1.w;
    }
    if (k < end) {
        int s0 = d_adj[k];
        float4 a0 = *(const float4*)&d_xl[(size_t)s0 * HC + ch];
        float m, p0 = 0.f;
        m = a0.x + xr4.x; m = (m > 0.f) ? m : NEG_SLOPE * m; p0 += m * av.x;
        m = a0.y + xr4.y; m = (m > 0.f) ? m : NEG_SLOPE * m; p0 += m * av.y;
        m = a0.z + xr4.z; m = (m > 0.f) ? m : NEG_SLOPE * m; p0 += m * av.z;
        m = a0.w + xr4.w; m = (m > 0.f) ? m : NEG_SLOPE * m; p0 += m * av.w;
        p0 += __shfl_xor_sync(0xffffffffu, p0, 8, 16);
        p0 += __shfl_xor_sync(0xffffffffu, p0, 4, 16);
        p0 += __shfl_xor_sync(0xffffffffu, p0, 2, 16);
        p0 += __shfl_xor_sync(0xffffffffu, p0, 1, 16);
        float w0 = __expf(p0);
        rsum += w0;
        acc.x += w0 * a0.x;
        acc.y += w0 * a0.y;
        acc.z += w0 * a0.z;
        acc.w += w0 * a0.w;
    }

    const float invd = 1.f / (rsum + 1e-16f);
    const float4 bv = *(const float4*)&bias[ch];
    float4 o;
    o.x = acc.x * invd + bv.x;
    o.y = acc.y * invd + bv.y;
    o.z = acc.z * invd + bv.z;
    o.w = acc.w * invd + bv.w;
    *(float4*)&d_acc[(size_t)w * HC + ch] = o;

    // ---- fused GraphNorm stats: reduce 8 nodes across the block ----
    *(float4*)&red[wwarp][ch] = o;
    __syncthreads();
    if (threadIdx.x < 128) {
        int c = threadIdx.x;
        float s = 0.f, q = 0.f;
#pragma unroll
        for (int j = 0; j < 8; j++) {
            float v = red[j][c];
            s += v;
            q += v * v;
        }
        atomicAdd(&d_sumF[statOff + c], s);
        atomicAdd(&d_sumsqF[statOff + c], q);
    }
}

// ---------------- fused MLP head: relu(norm(acc)@W1+b1)@W2+b2 ---------------
// GraphNorm+ReLU of layer-1 output applied on load (A,B from fused stats).
__global__ __launch_bounds__(256) void mlp_head(
    const float* __restrict__ W1, const float* __restrict__ b1,
    const float* __restrict__ W2, const float* __restrict__ b2,
    const float* __restrict__ gamma, const float* __restrict__ beta,
    const float* __restrict__ mscale, int statOff,
    float* __restrict__ out)
{
    __shared__ float W1s[128 * 64];
    __shared__ float W2s[128];
    __shared__ float b1s[64];
    __shared__ float xs[8][128];
    __shared__ float As[128], Bs[128];

    int tid = threadIdx.x;
    for (int i = tid; i < 128 * 64; i += 256) W1s[i] = W1[i];
    if (tid < 128) {
        W2s[tid] = W2[tid];
        int c = tid;
        float mean = d_sumF[statOff + c] * INV_N;
        float msq  = d_sumsqF[statOff + c] * INV_N;
        float mm   = mscale[c] * mean;
        float var  = msq - 2.f * mm * mean + mm * mm;
        float inv  = rsqrtf(var + EPS_GN);
        float A    = gamma[c] * inv;
        As[c] = A;
        Bs[c] = beta[c] - A * mm;
    }
    if (tid < 64) b1s[tid] = b1[tid];
    __syncthreads();

    int w = tid >> 5, lane = tid & 31;
    float bb0 = b2[0], bb1 = b2[1];
    int ch = lane * 4;
    float4 Av = *(const float4*)&As[ch];
    float4 Bv = *(const float4*)&Bs[ch];

    for (int n = blockIdx.x * 8 + w; n < N_NODES; n += gridDim.x * 8) {
        float4 v = *(const float4*)&d_acc[(size_t)n * HC + ch];
        v.x = fmaxf(Av.x * v.x + Bv.x, 0.f);
        v.y = fmaxf(Av.y * v.y + Bv.y, 0.f);
        v.z = fmaxf(Av.z * v.z + Bv.z, 0.f);
        v.w = fmaxf(Av.w * v.w + Bv.w, 0.f);
        *(float4*)&xs[w][ch] = v;
        __syncwarp();

        float h0 = b1s[lane], h1 = b1s[lane + 32];
#pragma unroll
        for (int k = 0; k < 128; k++) {
            float x = xs[w][k];
            h0 += x * W1s[k * 64 + lane];
            h1 += x * W1s[k * 64 + lane + 32];
        }
        h0 = (h0 > 0.f) ? h0 : 0.f;
        h1 = (h1 > 0.f) ? h1 : 0.f;

        float p0 = h0 * W2s[lane * 2]     + h1 * W2s[(lane + 32) * 2];
        float p1 = h0 * W2s[lane * 2 + 1] + h1 * W2s[(lane + 32) * 2 + 1];
#pragma unroll
        for (int off = 16; off > 0; off >>= 1) {
            p0 += __shfl_down_sync(0xffffffffu, p0, off);
            p1 += __shfl_down_sync(0xffffffffu, p1, off);
        }
        if (lane == 0) {
            out[n * 2]     = p0 + bb0;
            out[n * 2 + 1] = p1 + bb1;
        }
        __syncwarp();
    }
}

// ---------------- driver -----------------------------------------------------
extern "C" void kernel_launch(void* const* d_in, const int* in_sizes, int n_in,
                              void* d_out, int out_size)
{
    const float* x      = (const float*)d_in[0];
    const int*   ei     = (const int*)d_in[1];
    const float* Wl0 = (const float*)d_in[2];
    const float* bl0 = (const float*)d_in[3];
    const float* Wr0 = (const float*)d_in[4];
    const float* br0 = (const float*)d_in[5];
    const float* att0  = (const float*)d_in[6];
    const float* bias0 = (const float*)d_in[7];
    const float* Wl1 = (const float*)d_in[8];
    const float* bl1 = (const float*)d_in[9];
    const float* Wr1 = (const float*)d_in[10];
    const float* br1 = (const float*)d_in[11];
    const float* att1  = (const float*)d_in[12];
    const float* bias1 = (const float*)d_in[13];
    const float* g0  = (const float*)d_in[14];
    const float* be0 = (const float*)d_in[15];
    const float* ms0 = (const float*)d_in[16];
    const float* g1  = (const float*)d_in[17];
    const float* be1 = (const float*)d_in[18];
    const float* ms1 = (const float*)d_in[19];
    const float* W1 = (const float*)d_in[20];
    const float* b1 = (const float*)d_in[21];
    const float* W2 = (const float*)d_in[22];
    const float* b2 = (const float*)d_in[23];
    float* out = (float*)d_out;

    float *p_xl, *p_xr, *p_acc;
    cudaGetSymbolAddress((void**)&p_xl,  d_xl);
    cudaGetSymbolAddress((void**)&p_xr,  d_xr);
    cudaGetSymbolAddress((void**)&p_acc, d_acc);

    const dim3 gemm_grid((N_NODES + 63) / 64, 2);       // (782, 2)
    const int gat_grid  = (N_NODES * 32) / 256;         // 6250: exactly 1 warp/node

    // #1: layer-0 GEMM + fused degree count (d_deg starts zero each run)
    gemm_fused<<<gemm_grid, 256>>>(x, Wl0, bl0, Wr0, br0, p_xl, p_xr, ei,
                                   nullptr, nullptr, nullptr, 0);
    // #2: prefix sum (adds +1 self loop, resets d_deg for next replay)
    csr_scan<<<1, 1024>>>();
    // #3: adjacency scatter + zero both stat buffers
    csr_scatter<<<(ETOT + 255) / 256, 256>>>(ei);
    // #4: layer-0 GAT + stats  <-- profiler lands here
    gat_dst<<<gat_grid, 256>>>(att0, bias0, 0);

    // #5: layer-1 GEMM, GraphNorm0+ReLU fused into X load (reads d_acc)
    gemm_fused<<<gemm_grid, 256>>>(p_acc, Wl1, bl1, Wr1, br1, p_xl, p_xr,
                                   nullptr, g0, be0, ms0, 0);
    // #6: layer-1 GAT + stats
    gat_dst<<<gat_grid, 256>>>(att1, bias1, HC);

    // #7: MLP head, GraphNorm1+ReLU fused into feat load
    mlp_head<<<(N_NODES + 7) / 8, 256>>>(W1, b1, W2, b2,
                                         g1, be1, ms1, HC, out);
}